// round 11
// baseline (speedup 1.0000x reference)
#include <cuda_runtime.h>
#include <cuda_fp16.h>
#include <cstdint>
#include <cstddef>

// ---------------------------------------------------------------------------
// Fused GRU cell, fp16 tensor-core path (compute_103-safe PTX).
// R11: single fused fp32->fp16 convert kernel (1 launch), GEMM with 3-stage
// BK=64 pipeline + cp.async.wait_group 1 decoupling (the barrier waits on a
// fill issued two tiles ago -> never blocks), 2 CTAs/SM (84KB smem each).
//
// B operand rows (96), per wn slice s = wn*48:
//   rows [s+ 0,s+16): W_gate[n0+wn*16+u]     -> r (nb 0,1)
//   rows [s+16,s+32): W_gate[512+n0+wn*16+u] -> z (nb 2,3)
//   rows [s+32,s+48): Wi/Wh[n0+wn*16+u]      -> i/h (nb 4,5, phase split)
// kt<8: X=input, ih=Wi -> alo. kt>=8: X=hidden, ih=Wh -> ahi. (16 kt of BK=64)
// Epilogue uses ORIGINAL fp32 hidden for the z*h term.
// ---------------------------------------------------------------------------

// ---- fp16 scratch (device global: allocation-free) ----
static constexpr size_t OFF_IN  = 0;                        // 16384x512
static constexpr size_t OFF_HID = 8388608;                  // 16384x512
static constexpr size_t OFF_WG  = 16777216;                 // 1024x1024
static constexpr size_t OFF_WI  = 17825792;                 // 512x512
static constexpr size_t OFF_WH  = 18087936;                 // 512x512
static constexpr size_t CVT_TOTAL = 18350080;               // 35MB
__device__ __half g_cvt[CVT_TOTAL];

// segment bounds in float4 units
static constexpr int N4_IN  = 2097152;
static constexpr int N4_HID = 2097152;
static constexpr int N4_WG  = 262144;
static constexpr int N4_WI  = 65536;
static constexpr int N4_WH  = 65536;
static constexpr int N4_TOTAL = N4_IN + N4_HID + N4_WG + N4_WI + N4_WH; // 4587520

__global__ void cvt_all_kernel(const float4* __restrict__ input,
                               const float4* __restrict__ hidden,
                               const float4* __restrict__ Wg,
                               const float4* __restrict__ Wi,
                               const float4* __restrict__ Wh) {
    const int i = blockIdx.x * blockDim.x + threadIdx.x;
    if (i >= N4_TOTAL) return;
    const float4* src;
    size_t dst_off;
    int j = i;
    if (j < N4_IN)                 { src = input;  dst_off = OFF_IN; }
    else if ((j -= N4_IN) < N4_HID){ src = hidden; dst_off = OFF_HID; }
    else if ((j -= N4_HID) < N4_WG){ src = Wg;     dst_off = OFF_WG; }
    else if ((j -= N4_WG) < N4_WI) { src = Wi;     dst_off = OFF_WI; }
    else { j -= N4_WI;               src = Wh;     dst_off = OFF_WH; }
    const float4 v = src[j];
    __half2* dst = reinterpret_cast<__half2*>(g_cvt + dst_off);
    dst[2 * j]     = __floats2half2_rn(v.x, v.y);
    dst[2 * j + 1] = __floats2half2_rn(v.z, v.w);
}

// ---- helpers ----
#define SWZ(x) ((x) ^ (((x) >> 3) & 0x70))

__device__ __forceinline__ uint32_t smem_u32(const void* p) {
    uint32_t a;
    asm("{ .reg .u64 t; cvta.to.shared.u64 t, %1; cvt.u32.u64 %0, t; }"
        : "=r"(a) : "l"(p));
    return a;
}

__device__ __forceinline__ void cp16(uint32_t dst, const __half* src) {
    asm volatile("cp.async.cg.shared.global [%0], [%1], 16;"
                 :: "r"(dst), "l"(src) : "memory");
}
#define CP_COMMIT() asm volatile("cp.async.commit_group;" ::: "memory")
#define CP_WAIT1()  asm volatile("cp.async.wait_group 1;" ::: "memory")

__device__ __forceinline__ void ldsm4(uint32_t& r0, uint32_t& r1,
                                      uint32_t& r2, uint32_t& r3, uint32_t addr) {
    asm volatile("ldmatrix.sync.aligned.m8n8.x4.shared.b16 {%0,%1,%2,%3}, [%4];"
                 : "=r"(r0), "=r"(r1), "=r"(r2), "=r"(r3) : "r"(addr));
}

__device__ __forceinline__ void mma16(float* c, const uint32_t* a,
                                      uint32_t b0, uint32_t b1) {
    asm volatile(
        "mma.sync.aligned.m16n8k16.row.col.f32.f16.f16.f32 "
        "{%0,%1,%2,%3}, {%4,%5,%6,%7}, {%8,%9}, {%0,%1,%2,%3};"
        : "+f"(c[0]), "+f"(c[1]), "+f"(c[2]), "+f"(c[3])
        : "r"(a[0]), "r"(a[1]), "r"(a[2]), "r"(a[3]), "r"(b0), "r"(b1));
}

__device__ __forceinline__ float fsigmoid(float x) {
    return 1.0f / (1.0f + __expf(-x));
}
__device__ __forceinline__ float ftanh(float x) {
    float e = __expf(2.0f * x);          // overflow->inf, underflow->0: safe
    return 1.0f - 2.0f / (e + 1.0f);
}

// ---- geometry ----
// Rows are 128B (64 fp16), SW128 swizzled (classic Swizzle<3,4,3>).
static constexpr int A_BYTES     = 128 * 128;          // 16KB
static constexpr int B_BYTES     = 96 * 128;           // 12KB
static constexpr int STAGE_BYTES = A_BYTES + B_BYTES;  // 28672
static constexpr int SMEM_BYTES  = 128 + 3 * STAGE_BYTES;  // 86144/CTA

// fill offset for 16B-chunk index tid (8 chunks per 128B row); +4096 per
// extra 32 rows (row&7 invariant -> swizzle pattern invariant).
__device__ __forceinline__ uint32_t fill_off(int u) {
    const int r = u >> 3, cu = u & 7;
    return SWZ((uint32_t)(r * 128 + cu * 16));
}

// Compute one BK=64 tile (4 x k16); optionally interleave fill of stage fstg.
// 256 threads: A 4 chunks + B 3 chunks per thread, spread over ks 0..2.
template <bool PH, bool FILL>
__device__ __forceinline__ void compute_tile(
    uint32_t stg, uint32_t fstg, uint32_t aoff0, uint32_t boff0,
    uint32_t fA0, uint32_t fB0,
    const __half*& pA0, const __half* (&pB)[3],
    float (&alo)[2][6][4], float (&ahi)[2][2][4])
{
    uint32_t a[2][2][4];   // A double buffer [buf][mi][reg]
    uint32_t b[6][2];      // B single buffer

    #pragma unroll
    for (int mi = 0; mi < 2; mi++)
        ldsm4(a[0][mi][0], a[0][mi][1], a[0][mi][2], a[0][mi][3],
              stg + aoff0 + mi * 2048);
    #pragma unroll
    for (int p = 0; p < 3; p++)
        ldsm4(b[2 * p][0], b[2 * p][1], b[2 * p + 1][0], b[2 * p + 1][1],
              stg + boff0 + p * 2048);

    #pragma unroll
    for (int ks = 0; ks < 4; ks++) {
        const int cur = ks & 1, nxt = cur ^ 1;
        if (ks < 3) {
            const uint32_t kx = (uint32_t)((ks + 1) << 5);
            #pragma unroll
            for (int mi = 0; mi < 2; mi++)
                ldsm4(a[nxt][mi][0], a[nxt][mi][1], a[nxt][mi][2], a[nxt][mi][3],
                      stg + (aoff0 ^ kx) + mi * 2048);
        }
        if (FILL) {
            if (ks == 0) {             // A: 4 chunks
                #pragma unroll
                for (int i = 0; i < 4; i++)
                    cp16(fstg + fA0 + (uint32_t)i * 4096u, pA0 + i * 16384);
            } else if (ks == 1) {      // B: 2 chunks
                cp16(fstg + fB0,          pB[0]);
                cp16(fstg + fB0 + 4096u,  pB[1]);
            } else if (ks == 2) {      // B: 1 chunk + commit
                cp16(fstg + fB0 + 8192u,  pB[2]);
                CP_COMMIT();
            }
        }
        #pragma unroll
        for (int mi = 0; mi < 2; mi++) {
            #pragma unroll
            for (int nb = 0; nb < 6; nb++) {
                if (PH && nb >= 4)
                    mma16(ahi[mi][nb - 4], a[cur][mi], b[nb][0], b[nb][1]);
                else
                    mma16(alo[mi][nb], a[cur][mi], b[nb][0], b[nb][1]);
            }
        }
        if (ks < 3) {
            const uint32_t kx = (uint32_t)((ks + 1) << 5);
            #pragma unroll
            for (int p = 0; p < 3; p++)
                ldsm4(b[2 * p][0], b[2 * p][1], b[2 * p + 1][0], b[2 * p + 1][1],
                      stg + (boff0 ^ kx) + p * 2048);
        }
    }
    if (FILL) {
        pA0 += 64;
        #pragma unroll
        for (int i = 0; i < 3; i++) pB[i] += 64;
    }
}

__global__ void __launch_bounds__(256, 2)
gru_mma_kernel(const float* __restrict__ hidden,
               const float* __restrict__ bg, const float* __restrict__ bi,
               const float* __restrict__ bh, float* __restrict__ out)
{
    extern __shared__ char dsm[];
    const int tid  = threadIdx.x;
    const int lane = tid & 31;
    const int wid  = tid >> 5;
    const int wm   = wid >> 1;          // 0..3 (M, 32 rows each)
    const int wn   = wid & 1;           // 0..1 (N slice, 16 units each)
    const int n0 = blockIdx.x * 32;     // hidden-unit slice
    const int m0 = blockIdx.y * 128;    // batch-row slice

    const __half* cIn  = g_cvt + OFF_IN;
    const __half* cHid = g_cvt + OFF_HID;
    const __half* cWg  = g_cvt + OFF_WG;
    const __half* cWi  = g_cvt + OFF_WI;
    const __half* cWh  = g_cvt + OFF_WH;

    const uint32_t raw = smem_u32(dsm);
    const uint32_t sb  = (raw + 127u) & ~127u;
    const uint32_t stage0 = sb;   // stages at sb + s*STAGE_BYTES, s=0..2

    // ---- fill state (16B chunk = 8 halfs; 8 chunks per 128B row) ----
    const uint32_t fA0 = fill_off(tid);                        // + i*4096
    const uint32_t fB0 = (uint32_t)A_BYTES + fill_off(tid);    // + i*4096
    const int frow = tid >> 3, fcu = (tid & 7) * 8;            // frow 0..31
    const __half* pA0 = cIn + (m0 + frow) * 512 + fcu;         // + i*16384 halfs
    const __half* pB[3];
    bool isw[3];
    #pragma unroll
    for (int i = 0; i < 3; i++) {
        const int r = frow + 32 * i;        // 0..95
        const int ws = (r >= 48) ? 1 : 0, rr = r - ws * 48;
        const int un = n0 + ws * 16;
        isw[i] = (rr >= 32);
        if (rr < 16)       pB[i] = cWg + (un + rr) * 1024 + fcu;
        else if (rr < 32)  pB[i] = cWg + (512 + un + rr - 16) * 1024 + fcu;
        else               pB[i] = cWi + (un + rr - 32) * 512 + fcu;
    }
    // Phase switch (after 8 fills of +64): xa = in+row*512+512 -> hid+row*512.
    const ptrdiff_t dxa = (cHid - cIn) - 512;
    const ptrdiff_t dwh = (cWh - cWi) - 512;

    // ---- LDSM base offsets (128B rows; mi/p step = 16 rows = 2048B) ----
    uint32_t aoff0, boff0;
    {
        const uint32_t arow = (uint32_t)(wm * 32 + (lane & 7) + ((lane >> 3) & 1) * 8);
        const uint32_t acb  = (uint32_t)((lane >> 4) * 16);
        const uint32_t brow = (uint32_t)(wn * 48 + ((lane >> 4) * 8) + (lane & 7));
        const uint32_t bcb  = (uint32_t)(((lane >> 3) & 1) * 16);
        aoff0 = SWZ(arow * 128 + acb);
        boff0 = (uint32_t)A_BYTES + SWZ(brow * 128 + bcb);
    }

    float alo[2][6][4];
    float ahi[2][2][4];
    #pragma unroll
    for (int mi = 0; mi < 2; mi++) {
        #pragma unroll
        for (int nb = 0; nb < 6; nb++)
            #pragma unroll
            for (int e = 0; e < 4; e++) alo[mi][nb][e] = 0.0f;
        #pragma unroll
        for (int nb = 0; nb < 2; nb++)
            #pragma unroll
            for (int e = 0; e < 4; e++) ahi[mi][nb][e] = 0.0f;
    }

    // prologue: fill stages 0 and 1 (two committed groups)
    #pragma unroll
    for (int f = 0; f < 2; f++) {
        const uint32_t stg = stage0 + (uint32_t)f * STAGE_BYTES;
        #pragma unroll
        for (int i = 0; i < 4; i++)
            cp16(stg + fA0 + (uint32_t)i * 4096u, pA0 + i * 16384);
        pA0 += 64;
        #pragma unroll
        for (int i = 0; i < 3; i++) {
            cp16(stg + fB0 + (uint32_t)i * 4096u, pB[i]);
            pB[i] += 64;
        }
        CP_COMMIT();
    }

    // Mainloop: 16 kt. At kt top, outstanding groups = {fill(kt), fill(kt+1)};
    // wait_group 1 blocks only on fill(kt), issued two tiles ago -> free.
    // Barrier protects WAR: fill(kt+2) overwrites the stage compute(kt-1) read.
    uint32_t s_c = 0, s_f = 2 * (uint32_t)STAGE_BYTES;   // stage offsets mod 3
    #pragma unroll 1
    for (int kt = 0; kt < 8; kt++) {
        CP_WAIT1();
        __syncthreads();
        if (kt == 6) {   // next fill f=8: switch X -> hidden, Wi -> Wh
            pA0 += dxa;
            #pragma unroll
            for (int i = 0; i < 3; i++) if (isw[i]) pB[i] += dwh;
        }
        compute_tile<false, true>(stage0 + s_c, stage0 + s_f, aoff0, boff0,
                                  fA0, fB0, pA0, pB, alo, ahi);
        s_c += STAGE_BYTES; if (s_c == 3 * STAGE_BYTES) s_c = 0;
        s_f += STAGE_BYTES; if (s_f == 3 * STAGE_BYTES) s_f = 0;
    }
    #pragma unroll 1
    for (int kt = 8; kt < 14; kt++) {
        CP_WAIT1();
        __syncthreads();
        compute_tile<true, true>(stage0 + s_c, stage0 + s_f, aoff0, boff0,
                                 fA0, fB0, pA0, pB, alo, ahi);
        s_c += STAGE_BYTES; if (s_c == 3 * STAGE_BYTES) s_c = 0;
        s_f += STAGE_BYTES; if (s_f == 3 * STAGE_BYTES) s_f = 0;
    }
    #pragma unroll
    for (int kt = 14; kt < 16; kt++) {   // tail: no fills; empty commits keep
        CP_WAIT1();                      // the wait_group accounting correct
        __syncthreads();
        CP_COMMIT();
        compute_tile<true, false>(stage0 + s_c, stage0 + s_f, aoff0, boff0,
                                  fA0, fB0, pA0, pB, alo, ahi);
        s_c += STAGE_BYTES; if (s_c == 3 * STAGE_BYTES) s_c = 0;
    }

    // ---- register-resident epilogue (biases from global, fp32 hidden) ----
    #pragma unroll
    for (int mi = 0; mi < 2; mi++) {
        #pragma unroll
        for (int unb = 0; unb < 2; unb++) {
            const int ug = n0 + wn * 16 + unb * 8 + 2 * (lane & 3);  // global unit
            const float br0 = __ldg(&bg[ug]),        br1 = __ldg(&bg[ug + 1]);
            const float bz0 = __ldg(&bg[512 + ug]),  bz1 = __ldg(&bg[512 + ug + 1]);
            const float bi0 = __ldg(&bi[ug]),        bi1 = __ldg(&bi[ug + 1]);
            const float bh0 = __ldg(&bh[ug]),        bh1 = __ldg(&bh[ug + 1]);
            #pragma unroll
            for (int half = 0; half < 2; half++) {
                const int m = wm * 32 + mi * 16 + (lane >> 2) + 8 * half;
                const float rv0 = fsigmoid(alo[mi][0 + unb][2 * half]     + br0);
                const float rv1 = fsigmoid(alo[mi][0 + unb][2 * half + 1] + br1);
                const float zv0 = fsigmoid(alo[mi][2 + unb][2 * half]     + bz0);
                const float zv1 = fsigmoid(alo[mi][2 + unb][2 * half + 1] + bz1);
                const float iv0 = alo[mi][4 + unb][2 * half];
                const float iv1 = alo[mi][4 + unb][2 * half + 1];
                const float hv0 = ahi[mi][unb][2 * half];
                const float hv1 = ahi[mi][unb][2 * half + 1];
                const float2 hg = *(const float2*)&hidden[(m0 + m) * 512 + ug];
                const float ng0 = ftanh(iv0 + bi0 + rv0 * (hv0 + bh0));
                const float ng1 = ftanh(iv1 + bi1 + rv1 * (hv1 + bh1));
                float2 o;
                o.x = (1.0f - zv0) * ng0 + zv0 * hg.x;
                o.y = (1.0f - zv1) * ng1 + zv1 * hg.y;
                *(float2*)&out[(m0 + m) * 512 + ug] = o;
            }
        }
    }
}

extern "C" void kernel_launch(void* const* d_in, const int* in_sizes, int n_in,
                              void* d_out, int out_size)
{
    const float* input  = (const float*)d_in[0];
    const float* hidden = (const float*)d_in[1];
    const float* Wg     = (const float*)d_in[2];
    const float* bg     = (const float*)d_in[3];
    const float* Wi     = (const float*)d_in[4];
    const float* bi     = (const float*)d_in[5];
    const float* Wh     = (const float*)d_in[6];
    const float* bh     = (const float*)d_in[7];
    float* out = (float*)d_out;

    // single fused fp32 -> fp16 conversion pass
    cvt_all_kernel<<<(N4_TOTAL + 255) / 256, 256>>>(
        (const float4*)input, (const float4*)hidden,
        (const float4*)Wg, (const float4*)Wi, (const float4*)Wh);

    cudaFuncSetAttribute(gru_mma_kernel,
                         cudaFuncAttributeMaxDynamicSharedMemorySize, SMEM_BYTES);
    // grid.x = 16 n-slices of 32 units, grid.y = 128 batch tiles of 128 rows
    gru_mma_kernel<<<dim3(16, 128), 256, SMEM_BYTES>>>(hidden, bg, bi, bh, out);
}

// round 12
// speedup vs baseline: 1.0778x; 1.0778x over previous
#include <cuda_runtime.h>
#include <cuda_fp16.h>
#include <cstdint>
#include <cstddef>

// ---------------------------------------------------------------------------
// Fused GRU cell, fp16 tensor-core path (compute_103-safe PTX).
// R12: R10 GEMM structure (BK=128, 2-stage, 8 barriers, 2 CTAs/SM) with the
// fill committed early (A at ks0, B at ks1, commit ks1) so the next tile's
// cp.async.wait_group 0 has a ~6.5-ks completion window and never blocks.
// cvt pass in 3 launches: input, hidden, fused weights.
//
// B operand rows (96), per wn slice s = wn*48:
//   rows [s+ 0,s+16): W_gate[n0+wn*16+u]     -> r (nb 0,1)
//   rows [s+16,s+32): W_gate[512+n0+wn*16+u] -> z (nb 2,3)
//   rows [s+32,s+48): Wi/Wh[n0+wn*16+u]      -> i/h (nb 4,5, phase split)
// kt<4: X=input, ih=Wi -> alo. kt>=4: X=hidden, ih=Wh -> ahi.
// Epilogue uses ORIGINAL fp32 hidden for the z*h term.
// ---------------------------------------------------------------------------

// ---- fp16 scratch (device global: allocation-free) ----
static constexpr size_t OFF_IN  = 0;                        // 16384x512
static constexpr size_t OFF_HID = 8388608;                  // 16384x512
static constexpr size_t OFF_WG  = 16777216;                 // 1024x1024
static constexpr size_t OFF_WI  = 17825792;                 // 512x512
static constexpr size_t OFF_WH  = 18087936;                 // 512x512
static constexpr size_t CVT_TOTAL = 18350080;               // 35MB
__device__ __half g_cvt[CVT_TOTAL];

__global__ void cvt_kernel(const float4* __restrict__ src, size_t dst_off, int n4) {
    const int i = blockIdx.x * blockDim.x + threadIdx.x;
    if (i < n4) {
        const float4 v = src[i];
        __half2* dst = reinterpret_cast<__half2*>(g_cvt + dst_off);
        dst[2 * i]     = __floats2half2_rn(v.x, v.y);
        dst[2 * i + 1] = __floats2half2_rn(v.z, v.w);
    }
}

// fused weight conversion: Wg (262144 f4) + Wi (65536) + Wh (65536)
static constexpr int N4_WG = 262144, N4_WI = 65536, N4_WH = 65536;
static constexpr int N4_W_TOTAL = N4_WG + N4_WI + N4_WH;    // 393216
__global__ void cvt_w_kernel(const float4* __restrict__ Wg,
                             const float4* __restrict__ Wi,
                             const float4* __restrict__ Wh) {
    const int i = blockIdx.x * blockDim.x + threadIdx.x;
    if (i >= N4_W_TOTAL) return;
    const float4* src;
    size_t dst_off;
    int j = i;
    if (j < N4_WG)                { src = Wg; dst_off = OFF_WG; }
    else if ((j -= N4_WG) < N4_WI){ src = Wi; dst_off = OFF_WI; }
    else { j -= N4_WI;              src = Wh; dst_off = OFF_WH; }
    const float4 v = src[j];
    __half2* dst = reinterpret_cast<__half2*>(g_cvt + dst_off);
    dst[2 * j]     = __floats2half2_rn(v.x, v.y);
    dst[2 * j + 1] = __floats2half2_rn(v.z, v.w);
}

// ---- helpers ----
__device__ __forceinline__ uint32_t smem_u32(const void* p) {
    uint32_t a;
    asm("{ .reg .u64 t; cvta.to.shared.u64 t, %1; cvt.u32.u64 %0, t; }"
        : "=r"(a) : "l"(p));
    return a;
}

__device__ __forceinline__ void cp16(uint32_t dst, const __half* src) {
    asm volatile("cp.async.cg.shared.global [%0], [%1], 16;"
                 :: "r"(dst), "l"(src) : "memory");
}
#define CP_COMMIT() asm volatile("cp.async.commit_group;" ::: "memory")
#define CP_WAIT0()  asm volatile("cp.async.wait_group 0;" ::: "memory")

__device__ __forceinline__ void ldsm4(uint32_t& r0, uint32_t& r1,
                                      uint32_t& r2, uint32_t& r3, uint32_t addr) {
    asm volatile("ldmatrix.sync.aligned.m8n8.x4.shared.b16 {%0,%1,%2,%3}, [%4];"
                 : "=r"(r0), "=r"(r1), "=r"(r2), "=r"(r3) : "r"(addr));
}

__device__ __forceinline__ void mma16(float* c, const uint32_t* a,
                                      uint32_t b0, uint32_t b1) {
    asm volatile(
        "mma.sync.aligned.m16n8k16.row.col.f32.f16.f16.f32 "
        "{%0,%1,%2,%3}, {%4,%5,%6,%7}, {%8,%9}, {%0,%1,%2,%3};"
        : "+f"(c[0]), "+f"(c[1]), "+f"(c[2]), "+f"(c[3])
        : "r"(a[0]), "r"(a[1]), "r"(a[2]), "r"(a[3]), "r"(b0), "r"(b1));
}

__device__ __forceinline__ float fsigmoid(float x) {
    return 1.0f / (1.0f + __expf(-x));
}
__device__ __forceinline__ float ftanh(float x) {
    float e = __expf(2.0f * x);          // overflow->inf, underflow->0: safe
    return 1.0f - 2.0f / (e + 1.0f);
}

// ---- geometry ----
// Rows are 256B (128 fp16). Physical offset of (row, col byte c):
//   row*256 + (c>>7)*128 + ((c&127) ^ ((row&7)<<4))   [SW128 per 128B half]
static constexpr int A_BYTES     = 128 * 256;          // 32KB
static constexpr int B_BYTES     = 96 * 256;           // 24KB
static constexpr int STAGE_BYTES = A_BYTES + B_BYTES;  // 57344
static constexpr int SMEM_BYTES  = 128 + 2 * STAGE_BYTES;  // 114816/CTA

__device__ __forceinline__ uint32_t fill_off(int u) {
    const int r = u >> 4, cu = u & 15;
    return (uint32_t)(r * 256 + ((cu >> 3) << 7) + (((cu & 7) * 16) ^ ((r & 7) << 4)));
}

// Compute one BK=128 tile (8 x k16); optionally interleave next-stage fill.
// Fill schedule: A's 8 chunks at ks0, B's 6 chunks at ks1, COMMIT at ks1 —
// the next tile's wait_group 0 then has ~6.5 ks of completion window.
template <bool PH, bool FILL>
__device__ __forceinline__ void compute_tile(
    uint32_t stg, uint32_t fstg, uint32_t aoff0, uint32_t boff0,
    uint32_t fA0, uint32_t fB0,
    const __half*& pA0, const __half* (&pB)[6],
    float (&alo)[2][6][4], float (&ahi)[2][2][4])
{
    uint32_t a[2][2][4];   // A double buffer [buf][mi][reg]
    uint32_t b[6][2];      // B single buffer

    #pragma unroll
    for (int mi = 0; mi < 2; mi++)
        ldsm4(a[0][mi][0], a[0][mi][1], a[0][mi][2], a[0][mi][3],
              stg + aoff0 + mi * 4096);
    #pragma unroll
    for (int p = 0; p < 3; p++)
        ldsm4(b[2 * p][0], b[2 * p][1], b[2 * p + 1][0], b[2 * p + 1][1],
              stg + boff0 + p * 4096);

    #pragma unroll
    for (int ks = 0; ks < 8; ks++) {
        const int cur = ks & 1, nxt = cur ^ 1;
        if (ks < 7) {
            const uint32_t kx = (uint32_t)((ks + 1) << 5);
            #pragma unroll
            for (int mi = 0; mi < 2; mi++)
                ldsm4(a[nxt][mi][0], a[nxt][mi][1], a[nxt][mi][2], a[nxt][mi][3],
                      stg + (aoff0 ^ kx) + mi * 4096);
        }
        if (FILL) {
            if (ks == 0) {             // A: all 8 chunks
                #pragma unroll
                for (int j = 0; j < 8; j++)
                    cp16(fstg + fA0 + (uint32_t)j * 4096u, pA0 + j * 8192);
            } else if (ks == 1) {      // B: all 6 chunks + early commit
                #pragma unroll
                for (int i = 0; i < 6; i++)
                    cp16(fstg + fB0 + (uint32_t)i * 4096u, pB[i]);
                CP_COMMIT();
            }
        }
        #pragma unroll
        for (int mi = 0; mi < 2; mi++) {
            #pragma unroll
            for (int nb = 0; nb < 6; nb++) {
                if (PH && nb >= 4)
                    mma16(ahi[mi][nb - 4], a[cur][mi], b[nb][0], b[nb][1]);
                else
                    mma16(alo[mi][nb], a[cur][mi], b[nb][0], b[nb][1]);
            }
        }
        if (ks < 7) {
            const uint32_t kx = (uint32_t)((ks + 1) << 5);
            #pragma unroll
            for (int p = 0; p < 3; p++)
                ldsm4(b[2 * p][0], b[2 * p][1], b[2 * p + 1][0], b[2 * p + 1][1],
                      stg + (boff0 ^ kx) + p * 4096);
        }
    }
    if (FILL) {
        pA0 += 128;
        #pragma unroll
        for (int i = 0; i < 6; i++) pB[i] += 128;
    }
}

__global__ void __launch_bounds__(256, 2)
gru_mma_kernel(const float* __restrict__ hidden,
               const float* __restrict__ bg, const float* __restrict__ bi,
               const float* __restrict__ bh, float* __restrict__ out)
{
    extern __shared__ char dsm[];
    const int tid  = threadIdx.x;
    const int lane = tid & 31;
    const int wid  = tid >> 5;
    const int wm   = wid >> 1;          // 0..3 (M, 32 rows each)
    const int wn   = wid & 1;           // 0..1 (N slice, 16 units each)
    const int n0 = blockIdx.x * 32;     // hidden-unit slice
    const int m0 = blockIdx.y * 128;    // batch-row slice

    const __half* cIn  = g_cvt + OFF_IN;
    const __half* cHid = g_cvt + OFF_HID;
    const __half* cWg  = g_cvt + OFF_WG;
    const __half* cWi  = g_cvt + OFF_WI;
    const __half* cWh  = g_cvt + OFF_WH;

    const uint32_t raw = smem_u32(dsm);
    const uint32_t sb  = (raw + 127u) & ~127u;
    const uint32_t stage0 = sb;
    const uint32_t stage1 = stage0 + STAGE_BYTES;

    // ---- fill state (16B chunk = 8 halfs; 16 chunks per 256B row) ----
    const uint32_t fA0 = fill_off(tid);                        // + j*4096
    const uint32_t fB0 = (uint32_t)A_BYTES + fill_off(tid);    // + i*4096
    const int frow = tid >> 4, fcu = (tid & 15) * 8;
    const __half* pA0 = cIn + (m0 + frow) * 512 + fcu;         // + j*8192 halfs
    const __half* pB[6];
    bool isw[6];
    #pragma unroll
    for (int i = 0; i < 6; i++) {
        const int r = frow + 16 * i;        // 0..95
        const int ws = (r >= 48) ? 1 : 0, rr = r - ws * 48;
        const int un = n0 + ws * 16;
        isw[i] = (rr >= 32);
        if (rr < 16)       pB[i] = cWg + (un + rr) * 1024 + fcu;
        else if (rr < 32)  pB[i] = cWg + (512 + un + rr - 16) * 1024 + fcu;
        else               pB[i] = cWi + (un + rr - 32) * 512 + fcu;
    }
    // Phase switch (after 4 fills of +128): xa = in+row*512+512 -> hid+row*512.
    const ptrdiff_t dxa = (cHid - cIn) - 512;
    const ptrdiff_t dwh = (cWh - cWi) - 512;

    // ---- LDSM base offsets ----
    uint32_t aoff0, boff0;
    {
        const uint32_t arow = (uint32_t)(wm * 32 + (lane & 7) + ((lane >> 3) & 1) * 8);
        const uint32_t acb  = (uint32_t)((lane >> 4) * 16);
        const uint32_t brow = (uint32_t)(wn * 48 + ((lane >> 4) * 8) + (lane & 7));
        const uint32_t bcb  = (uint32_t)(((lane >> 3) & 1) * 16);
        aoff0 = arow * 256 + (acb ^ ((arow & 7) << 4));                     // + mi*4096
        boff0 = (uint32_t)A_BYTES + brow * 256 + (bcb ^ ((brow & 7) << 4)); // + p*4096
    }

    float alo[2][6][4];
    float ahi[2][2][4];
    #pragma unroll
    for (int mi = 0; mi < 2; mi++) {
        #pragma unroll
        for (int nb = 0; nb < 6; nb++)
            #pragma unroll
            for (int e = 0; e < 4; e++) alo[mi][nb][e] = 0.0f;
        #pragma unroll
        for (int nb = 0; nb < 2; nb++)
            #pragma unroll
            for (int e = 0; e < 4; e++) ahi[mi][nb][e] = 0.0f;
    }

    // prologue: fill stage0 for kt=0
    {
        #pragma unroll
        for (int j = 0; j < 8; j++)
            cp16(stage0 + fA0 + (uint32_t)j * 4096u, pA0 + j * 8192);
        pA0 += 128;
        #pragma unroll
        for (int i = 0; i < 6; i++) {
            cp16(stage0 + fB0 + (uint32_t)i * 4096u, pB[i]);
            pB[i] += 128;
        }
        CP_COMMIT();
    }

    // Phase 0: kt = 0..3 (X=input, ih=Wi -> alo)
    #pragma unroll 2
    for (int kt = 0; kt < 4; kt++) {
        const uint32_t stg  = (kt & 1) ? stage1 : stage0;
        const uint32_t fstg = (kt & 1) ? stage0 : stage1;
        CP_WAIT0();
        __syncthreads();
        if (kt == 3) {   // next fill f=4: switch xa->hidden, Wi->Wh
            pA0 += dxa;
            #pragma unroll
            for (int i = 0; i < 6; i++) if (isw[i]) pB[i] += dwh;
        }
        compute_tile<false, true>(stg, fstg, aoff0, boff0, fA0, fB0,
                                  pA0, pB, alo, ahi);
    }
    // Phase 1: kt = 4..7 (X=hidden, ih=Wh -> ahi); last iter fills nothing.
    #pragma unroll 2
    for (int kt = 4; kt < 7; kt++) {
        const uint32_t stg  = (kt & 1) ? stage1 : stage0;
        const uint32_t fstg = (kt & 1) ? stage0 : stage1;
        CP_WAIT0();
        __syncthreads();
        compute_tile<true, true>(stg, fstg, aoff0, boff0, fA0, fB0,
                                 pA0, pB, alo, ahi);
    }
    {
        CP_WAIT0();
        __syncthreads();
        compute_tile<true, false>(stage1, stage0, aoff0, boff0, fA0, fB0,
                                  pA0, pB, alo, ahi);
    }

    // ---- register-resident epilogue (biases from global, fp32 hidden) ----
    #pragma unroll
    for (int mi = 0; mi < 2; mi++) {
        #pragma unroll
        for (int unb = 0; unb < 2; unb++) {
            const int ug = n0 + wn * 16 + unb * 8 + 2 * (lane & 3);  // global unit
            const float br0 = __ldg(&bg[ug]),        br1 = __ldg(&bg[ug + 1]);
            const float bz0 = __ldg(&bg[512 + ug]),  bz1 = __ldg(&bg[512 + ug + 1]);
            const float bi0 = __ldg(&bi[ug]),        bi1 = __ldg(&bi[ug + 1]);
            const float bh0 = __ldg(&bh[ug]),        bh1 = __ldg(&bh[ug + 1]);
            #pragma unroll
            for (int half = 0; half < 2; half++) {
                const int m = wm * 32 + mi * 16 + (lane >> 2) + 8 * half;
                const float rv0 = fsigmoid(alo[mi][0 + unb][2 * half]     + br0);
                const float rv1 = fsigmoid(alo[mi][0 + unb][2 * half + 1] + br1);
                const float zv0 = fsigmoid(alo[mi][2 + unb][2 * half]     + bz0);
                const float zv1 = fsigmoid(alo[mi][2 + unb][2 * half + 1] + bz1);
                const float iv0 = alo[mi][4 + unb][2 * half];
                const float iv1 = alo[mi][4 + unb][2 * half + 1];
                const float hv0 = ahi[mi][unb][2 * half];
                const float hv1 = ahi[mi][unb][2 * half + 1];
                const float2 hg = *(const float2*)&hidden[(m0 + m) * 512 + ug];
                const float ng0 = ftanh(iv0 + bi0 + rv0 * (hv0 + bh0));
                const float ng1 = ftanh(iv1 + bi1 + rv1 * (hv1 + bh1));
                float2 o;
                o.x = (1.0f - zv0) * ng0 + zv0 * hg.x;
                o.y = (1.0f - zv1) * ng1 + zv1 * hg.y;
                *(float2*)&out[(m0 + m) * 512 + ug] = o;
            }
        }
    }
}

extern "C" void kernel_launch(void* const* d_in, const int* in_sizes, int n_in,
                              void* d_out, int out_size)
{
    const float* input  = (const float*)d_in[0];
    const float* hidden = (const float*)d_in[1];
    const float* Wg     = (const float*)d_in[2];
    const float* bg     = (const float*)d_in[3];
    const float* Wi     = (const float*)d_in[4];
    const float* bi     = (const float*)d_in[5];
    const float* Wh     = (const float*)d_in[6];
    const float* bh     = (const float*)d_in[7];
    float* out = (float*)d_out;

    // fp32 -> fp16 conversion: big arrays on the simple path, weights fused
    cvt_kernel<<<(2097152 + 255) / 256, 256>>>((const float4*)input,  OFF_IN,  2097152);
    cvt_kernel<<<(2097152 + 255) / 256, 256>>>((const float4*)hidden, OFF_HID, 2097152);
    cvt_w_kernel<<<(N4_W_TOTAL + 255) / 256, 256>>>(
        (const float4*)Wg, (const float4*)Wi, (const float4*)Wh);

    cudaFuncSetAttribute(gru_mma_kernel,
                         cudaFuncAttributeMaxDynamicSharedMemorySize, SMEM_BYTES);
    // grid.x = 16 n-slices of 32 units, grid.y = 128 batch tiles of 128 rows
    gru_mma_kernel<<<dim3(16, 128), 256, SMEM_BYTES>>>(hidden, bg, bi, bh, out);
}